// round 15
// baseline (speedup 1.0000x reference)
#include <cuda_runtime.h>

#define BN 8
#define CC 64
#define MM 256
#define NNX 256
#define MN (MM*NNX)          // 65536
#define TOTPIX (BN*MN)       // 524288

__device__ float g_avg[TOTPIX];
__device__ float g_mx [TOTPIX];
__device__ float g_sa [TOTPIX];
__device__ float g_gam[TOTPIX];
__device__ float g_bet[TOTPIX];
__device__ unsigned char g_mask[TOTPIX];
__device__ double g_stats[CC*4];      // s1, q1, s2, q2 per channel
__device__ unsigned int g_np;

// ---------------- K1: channel avg + max, 2 pixels/thread (float2), batched loads ----------------
__global__ void __launch_bounds__(256, 8) k1_avgmax(const float* __restrict__ x) {
    const int t = threadIdx.x;
    if (blockIdx.x == 0) {
        if (t < CC*4) g_stats[t] = 0.0;
        if (t == 0)   g_np = 0u;
    }
    const int tid  = blockIdx.x * 256 + t;
    const int base = tid * 2;                 // 2 pixels per thread
    const int b    = base >> 16;
    const int pix  = base & (MN - 1);
    const float* xb = x + ((size_t)b << 22) + pix;

    float2 s, mx;
#pragma unroll
    for (int g = 0; g < 8; g++) {
        float2 v[8];
#pragma unroll
        for (int j = 0; j < 8; j++)
            v[j] = *(const float2*)(xb + ((size_t)(g * 8 + j) << 16));
#pragma unroll
        for (int j = 0; j < 8; j++) {
            if (g == 0 && j == 0) { s = v[0]; mx = v[0]; }
            else {
                s.x += v[j].x; s.y += v[j].y;
                mx.x = fmaxf(mx.x, v[j].x); mx.y = fmaxf(mx.y, v[j].y);
            }
        }
    }
    const float inv = 1.0f / 64.0f;
    float2 a; a.x = s.x * inv; a.y = s.y * inv;
    *(float2*)(g_avg + base) = a;
    *(float2*)(g_mx  + base) = mx;
}

// ---------------- K23s: sa conv + mask + Np only (1 quad/thread) ----------------
__global__ void k23s_conv(const float* __restrict__ w1) {
    __shared__ float sAvg[22][80];
    __shared__ float sMax[22][80];
    __shared__ float sw1[98];
    const int b  = blockIdx.z;
    const int x0 = blockIdx.x * 64, y0 = blockIdx.y * 16;
    const int t  = threadIdx.x;
    if (t < 98) sw1[t] = w1[t];

    const float* A = g_avg + b * MN;
    const float* X = g_mx  + b * MN;
    for (int i = t; i < 22 * 70; i += 256) {
        int sy = i / 70, sx = i % 70;
        int gy = y0 + sy - 3, gx = x0 + sx - 3;
        float a = 0.f, m = 0.f;
        if ((unsigned)gy < 256u && (unsigned)gx < 256u) {
            int g = gy * 256 + gx; a = A[g]; m = X[g];
        }
        sAvg[sy][sx] = a; sMax[sy][sx] = m;
    }
    __syncthreads();

    const int row = t >> 4;          // 0..15
    const int cq  = (t & 15) * 4;    // 0..60
    float acc0 = 0.f, acc1 = 0.f, acc2 = 0.f, acc3 = 0.f;
#pragma unroll
    for (int ky = 0; ky < 7; ky++) {
        const float* ra = &sAvg[row + ky][cq];
        const float* rm = &sMax[row + ky][cq];
        float4 a0 = *(const float4*)ra;
        float4 a1 = *(const float4*)(ra + 4);
        float4 a2 = *(const float4*)(ra + 8);
        float4 m0 = *(const float4*)rm;
        float4 m1 = *(const float4*)(rm + 4);
        float4 m2 = *(const float4*)(rm + 8);
        float av[12] = {a0.x,a0.y,a0.z,a0.w,a1.x,a1.y,a1.z,a1.w,a2.x,a2.y,a2.z,a2.w};
        float mv[12] = {m0.x,m0.y,m0.z,m0.w,m1.x,m1.y,m1.z,m1.w,m2.x,m2.y,m2.z,m2.w};
#pragma unroll
        for (int kx = 0; kx < 7; kx++) {
            float wa = sw1[ky*7 + kx], wm = sw1[49 + ky*7 + kx];
            acc0 = fmaf(av[kx  ], wa, acc0); acc0 = fmaf(mv[kx  ], wm, acc0);
            acc1 = fmaf(av[kx+1], wa, acc1); acc1 = fmaf(mv[kx+1], wm, acc1);
            acc2 = fmaf(av[kx+2], wa, acc2); acc2 = fmaf(mv[kx+2], wm, acc2);
            acc3 = fmaf(av[kx+3], wa, acc3); acc3 = fmaf(mv[kx+3], wm, acc3);
        }
    }
    float4 sa;
    sa.x = 1.f / (1.f + expf(-acc0));
    sa.y = 1.f / (1.f + expf(-acc1));
    sa.z = 1.f / (1.f + expf(-acc2));
    sa.w = 1.f / (1.f + expf(-acc3));
    const int idx = b * MN + (y0 + row) * 256 + x0 + cq;
    *(float4*)(g_sa + idx) = sa;
    uchar4 mk;
    mk.x = sa.x >= 0.8f ? 1 : 0;
    mk.y = sa.y >= 0.8f ? 1 : 0;
    mk.z = sa.z >= 0.8f ? 1 : 0;
    mk.w = sa.w >= 0.8f ? 1 : 0;
    *(uchar4*)(g_mask + idx) = mk;
    int cnt = (int)mk.x + mk.y + mk.z + mk.w;
    unsigned tot = __reduce_add_sync(0xffffffffu, (unsigned)cnt);
    if ((t & 31) == 0 && tot) atomicAdd(&g_np, tot);
}

// ---------------- K45: gamma/beta conv blocks (0..511) + stats blocks (512..2559) ----------------
#define CONV_BLOCKS 512
#define STAT_BLOCKS (BN*CC*4)
__global__ void __launch_bounds__(256, 8) k45_fused(const float* __restrict__ x,
                                                    const float* __restrict__ wg, const float* __restrict__ bg,
                                                    const float* __restrict__ wb, const float* __restrict__ bb) {
    const int bx = blockIdx.x;
    const int t  = threadIdx.x;

    if (bx >= CONV_BLOCKS) {
        // ---- stats path ----
        const int sb    = bx - CONV_BLOCKS;
        const int chunk = sb & 3;
        const int c     = (sb >> 2) & 63;
        const int b     = sb >> 8;
        const float* xp = x + (((size_t)(b * CC + c)) << 16) + chunk * 16384;
        const unsigned char* mp = g_mask + (b << 16) + chunk * 16384;
        float s1 = 0.f, q1 = 0.f, s2 = 0.f, q2 = 0.f;
#pragma unroll
        for (int g = 0; g < 4; g++) {
            float4 xv[4]; uchar4 mk[4];
#pragma unroll
            for (int j = 0; j < 4; j++) {
                int off = ((g * 4 + j) * 256 + t) * 4;
                xv[j] = *(const float4*)(xp + off);
                mk[j] = *(const uchar4*)(mp + off);
            }
#pragma unroll
            for (int j = 0; j < 4; j++) {
                float m, n;
                m = mk[j].x ? 1.f : 0.f; n = 1.f - m;
                s1 = fmaf(m, xv[j].x, s1); q1 = fmaf(m * xv[j].x, xv[j].x, q1);
                s2 = fmaf(n, xv[j].x, s2); q2 = fmaf(n * xv[j].x, xv[j].x, q2);
                m = mk[j].y ? 1.f : 0.f; n = 1.f - m;
                s1 = fmaf(m, xv[j].y, s1); q1 = fmaf(m * xv[j].y, xv[j].y, q1);
                s2 = fmaf(n, xv[j].y, s2); q2 = fmaf(n * xv[j].y, xv[j].y, q2);
                m = mk[j].z ? 1.f : 0.f; n = 1.f - m;
                s1 = fmaf(m, xv[j].z, s1); q1 = fmaf(m * xv[j].z, xv[j].z, q1);
                s2 = fmaf(n, xv[j].z, s2); q2 = fmaf(n * xv[j].z, xv[j].z, q2);
                m = mk[j].w ? 1.f : 0.f; n = 1.f - m;
                s1 = fmaf(m, xv[j].w, s1); q1 = fmaf(m * xv[j].w, xv[j].w, q1);
                s2 = fmaf(n, xv[j].w, s2); q2 = fmaf(n * xv[j].w, xv[j].w, q2);
            }
        }
#pragma unroll
        for (int o = 16; o; o >>= 1) {
            s1 += __shfl_down_sync(0xffffffffu, s1, o);
            q1 += __shfl_down_sync(0xffffffffu, q1, o);
            s2 += __shfl_down_sync(0xffffffffu, s2, o);
            q2 += __shfl_down_sync(0xffffffffu, q2, o);
        }
        __shared__ float sh[8][4];
        int lane = t & 31, w = t >> 5;
        if (lane == 0) { sh[w][0] = s1; sh[w][1] = q1; sh[w][2] = s2; sh[w][3] = q2; }
        __syncthreads();
        if (t < 4) {
            float v = 0.f;
#pragma unroll
            for (int i = 0; i < 8; i++) v += sh[i][t];
            atomicAdd(&g_stats[c * 4 + t], (double)v);
        }
    } else {
        // ---- gamma/beta conv path: two 4-accumulator passes to fit 32 regs ----
        __shared__ float sSa[22][80];
        __shared__ float swt[98];     // [0..48]=wg, [49..97]=wb
        const int i  = bx;
        const int x0 = (i & 3) * 64;
        const int y0 = ((i >> 2) & 15) * 16;
        const int b  = i >> 6;
        if (t < 49)             swt[t] = wg[t];
        else if (t < 98)        swt[t] = wb[t - 49];
        const float* S = g_sa + b * MN;
        for (int j = t; j < 22 * 70; j += 256) {
            int sy = j / 70, sx = j % 70;
            int gy = y0 + sy - 3, gx = x0 + sx - 3;
            float v = 0.f;
            if ((unsigned)gy < 256u && (unsigned)gx < 256u) v = S[gy * 256 + gx];
            sSa[sy][sx] = v;
        }
        __syncthreads();
        const int row = t >> 4;
        const int cq  = (t & 15) * 4;
        const int idx = b * MN + (y0 + row) * 256 + x0 + cq;
#pragma unroll
        for (int pass = 0; pass < 2; pass++) {
            const float* wgt = &swt[pass * 49];
            float a0 = 0.f, a1 = 0.f, a2 = 0.f, a3 = 0.f;
#pragma unroll
            for (int ky = 0; ky < 7; ky++) {
                const float* rs = &sSa[row + ky][cq];
                float4 s0 = *(const float4*)rs;
                float4 s1 = *(const float4*)(rs + 4);
                float4 s2 = *(const float4*)(rs + 8);
                float sv[12] = {s0.x,s0.y,s0.z,s0.w,s1.x,s1.y,s1.z,s1.w,s2.x,s2.y,s2.z,s2.w};
#pragma unroll
                for (int kx = 0; kx < 7; kx++) {
                    float wv = wgt[ky*7 + kx];
                    a0 = fmaf(sv[kx  ], wv, a0);
                    a1 = fmaf(sv[kx+1], wv, a1);
                    a2 = fmaf(sv[kx+2], wv, a2);
                    a3 = fmaf(sv[kx+3], wv, a3);
                }
            }
            if (pass == 0) {
                const float bgv = bg[0];
                float4 go; go.x = a0 + bgv; go.y = a1 + bgv; go.z = a2 + bgv; go.w = a3 + bgv;
                *(float4*)(g_gam + idx) = go;
            } else {
                const float bbv = bb[0];
                float4 bo; bo.x = a0 + bbv; bo.y = a1 + bbv; bo.z = a2 + bbv; bo.w = a3 + bbv;
                *(float4*)(g_bet + idx) = bo;
            }
        }
    }
}

// ---------------- K6: params (fp32) + fused output; 1 quad/thread, 16 channels/block ----------------
__global__ void __launch_bounds__(256, 8) k6_out(const float* __restrict__ x, float* __restrict__ out) {
    __shared__ float4 sp[CC];
    const int t = threadIdx.x;
    if (t < CC) {
        float s1 = (float)g_stats[t*4+0], q1 = (float)g_stats[t*4+1];
        float s2 = (float)g_stats[t*4+2], q2 = (float)g_stats[t*4+3];
        float np = (float)g_np;
        float nq = (float)TOTPIX - np;
        float Sr1 = np > 0.f ? np : 1.f;
        float Sr2 = nq > 0.f ? nq : 1.f;
        float mu1 = s1 / Sr1, mu2 = s2 / Sr2;
        const float nt = (float)TOTPIX;
        float v1 = (q1 - s1 * mu1) / nt;
        float v2 = (q2 - s2 * mu2) / nt;
        v1 = fmaxf(v1, 0.f);
        v2 = fmaxf(v2, 0.f);
        float a1 = sqrtf(Sr1 / nt) * rsqrtf(v1 + 1e-5f);
        float a2 = sqrtf(Sr2 / nt) * rsqrtf(v2 + 1e-5f);
        float4 p; p.x = mu1; p.y = a1; p.z = mu2; p.w = a2;
        sp[t] = p;
    }
    __syncthreads();
    const int tid  = blockIdx.x * 256 + t;
    const int base = tid * 4;
    const int b    = base >> 16;
    const int pix  = base & (MN - 1);
    const int c0   = blockIdx.y * 16;               // channel group: 0, 16, 32, 48

    uchar4 mk = *(const uchar4*)(g_mask + base);
    float4 gm = *(const float4*)(g_gam + base);
    float4 bt = *(const float4*)(g_bet + base);
    float g0 = 1.f + gm.x, g1 = 1.f + gm.y, g2 = 1.f + gm.z, g3 = 1.f + gm.w;
    const float* xb = x   + ((size_t)(b * CC + c0) << 16) + pix;
    float*       ob = out + ((size_t)(b * CC + c0) << 16) + pix;
#pragma unroll 4
    for (int c = 0; c < 16; c++) {
        float4 xv = *(const float4*)(xb + ((size_t)c << 16));
        float4 p  = sp[c0 + c];
        float4 o;
        float mu, a;
        mu = mk.x ? p.x : p.z; a = mk.x ? p.y : p.w; o.x = (xv.x - mu) * (a * g0) + bt.x;
        mu = mk.y ? p.x : p.z; a = mk.y ? p.y : p.w; o.y = (xv.y - mu) * (a * g1) + bt.y;
        mu = mk.z ? p.x : p.z; a = mk.z ? p.y : p.w; o.z = (xv.z - mu) * (a * g2) + bt.z;
        mu = mk.w ? p.x : p.z; a = mk.w ? p.y : p.w; o.w = (xv.w - mu) * (a * g3) + bt.w;
        *(float4*)(ob + ((size_t)c << 16)) = o;
    }
}

extern "C" void kernel_launch(void* const* d_in, const int* in_sizes, int n_in,
                              void* d_out, int out_size) {
    const float* x  = (const float*)d_in[0];
    const float* w1 = (const float*)d_in[1];
    const float* wg = (const float*)d_in[2];
    const float* bg = (const float*)d_in[3];
    const float* wb = (const float*)d_in[4];
    const float* bb = (const float*)d_in[5];
    float* out = (float*)d_out;

    k1_avgmax<<<TOTPIX / 512, 256>>>(x);
    k23s_conv<<<dim3(4, 16, BN), 256>>>(w1);
    k45_fused<<<CONV_BLOCKS + STAT_BLOCKS, 256>>>(x, wg, bg, wb, bb);
    k6_out<<<dim3(TOTPIX / 1024, 4), 256>>>(x, out);
}

// round 16
// speedup vs baseline: 1.0167x; 1.0167x over previous
#include <cuda_runtime.h>

#define BN 8
#define CC 64
#define MM 256
#define NNX 256
#define MN (MM*NNX)          // 65536
#define TOTPIX (BN*MN)       // 524288

__device__ float g_avg[TOTPIX];
__device__ float g_mx [TOTPIX];
__device__ float g_sa [TOTPIX];
__device__ float g_gam[TOTPIX];
__device__ float g_bet[TOTPIX];
__device__ unsigned char g_mask[TOTPIX];
__device__ double g_stats[CC*4];      // s1, q1, s2, q2 per channel
__device__ unsigned int g_np;

// ---------------- K1: channel avg + max, 4 px/thread, 8-deep load batches ----------------
__global__ void __launch_bounds__(256, 4) k1_avgmax(const float* __restrict__ x) {
    const int t = threadIdx.x;
    if (blockIdx.x == 0) {
        if (t < CC*4) g_stats[t] = 0.0;
        if (t == 0)   g_np = 0u;
    }
    const int tid  = blockIdx.x * 256 + t;
    const int base = tid * 4;
    const int b    = base >> 16;
    const int pix  = base & (MN - 1);
    const float* xb = x + ((size_t)b << 22) + pix;

    float4 s, mx;
#pragma unroll
    for (int g = 0; g < 8; g++) {
        float4 v[8];
#pragma unroll
        for (int j = 0; j < 8; j++)
            v[j] = *(const float4*)(xb + ((size_t)(g * 8 + j) << 16));
#pragma unroll
        for (int j = 0; j < 8; j++) {
            if (g == 0 && j == 0) { s = v[0]; mx = v[0]; }
            else {
                s.x += v[j].x; s.y += v[j].y; s.z += v[j].z; s.w += v[j].w;
                mx.x = fmaxf(mx.x, v[j].x); mx.y = fmaxf(mx.y, v[j].y);
                mx.z = fmaxf(mx.z, v[j].z); mx.w = fmaxf(mx.w, v[j].w);
            }
        }
    }
    const float inv = 1.0f / 64.0f;
    float4 a; a.x = s.x*inv; a.y = s.y*inv; a.z = s.z*inv; a.w = s.w*inv;
    *(float4*)(g_avg + base) = a;
    *(float4*)(g_mx  + base) = mx;
}

// ---------------- K23s: sa conv + mask + Np only (1 quad/thread) ----------------
__global__ void k23s_conv(const float* __restrict__ w1) {
    __shared__ float sAvg[22][80];
    __shared__ float sMax[22][80];
    __shared__ float sw1[98];
    const int b  = blockIdx.z;
    const int x0 = blockIdx.x * 64, y0 = blockIdx.y * 16;
    const int t  = threadIdx.x;
    if (t < 98) sw1[t] = w1[t];

    const float* A = g_avg + b * MN;
    const float* X = g_mx  + b * MN;
    for (int i = t; i < 22 * 70; i += 256) {
        int sy = i / 70, sx = i % 70;
        int gy = y0 + sy - 3, gx = x0 + sx - 3;
        float a = 0.f, m = 0.f;
        if ((unsigned)gy < 256u && (unsigned)gx < 256u) {
            int g = gy * 256 + gx; a = A[g]; m = X[g];
        }
        sAvg[sy][sx] = a; sMax[sy][sx] = m;
    }
    __syncthreads();

    const int row = t >> 4;          // 0..15
    const int cq  = (t & 15) * 4;    // 0..60
    float acc0 = 0.f, acc1 = 0.f, acc2 = 0.f, acc3 = 0.f;
#pragma unroll
    for (int ky = 0; ky < 7; ky++) {
        const float* ra = &sAvg[row + ky][cq];
        const float* rm = &sMax[row + ky][cq];
        float4 a0 = *(const float4*)ra;
        float4 a1 = *(const float4*)(ra + 4);
        float4 a2 = *(const float4*)(ra + 8);
        float4 m0 = *(const float4*)rm;
        float4 m1 = *(const float4*)(rm + 4);
        float4 m2 = *(const float4*)(rm + 8);
        float av[12] = {a0.x,a0.y,a0.z,a0.w,a1.x,a1.y,a1.z,a1.w,a2.x,a2.y,a2.z,a2.w};
        float mv[12] = {m0.x,m0.y,m0.z,m0.w,m1.x,m1.y,m1.z,m1.w,m2.x,m2.y,m2.z,m2.w};
#pragma unroll
        for (int kx = 0; kx < 7; kx++) {
            float wa = sw1[ky*7 + kx], wm = sw1[49 + ky*7 + kx];
            acc0 = fmaf(av[kx  ], wa, acc0); acc0 = fmaf(mv[kx  ], wm, acc0);
            acc1 = fmaf(av[kx+1], wa, acc1); acc1 = fmaf(mv[kx+1], wm, acc1);
            acc2 = fmaf(av[kx+2], wa, acc2); acc2 = fmaf(mv[kx+2], wm, acc2);
            acc3 = fmaf(av[kx+3], wa, acc3); acc3 = fmaf(mv[kx+3], wm, acc3);
        }
    }
    float4 sa;
    sa.x = 1.f / (1.f + expf(-acc0));
    sa.y = 1.f / (1.f + expf(-acc1));
    sa.z = 1.f / (1.f + expf(-acc2));
    sa.w = 1.f / (1.f + expf(-acc3));
    const int idx = b * MN + (y0 + row) * 256 + x0 + cq;
    *(float4*)(g_sa + idx) = sa;
    uchar4 mk;
    mk.x = sa.x >= 0.8f ? 1 : 0;
    mk.y = sa.y >= 0.8f ? 1 : 0;
    mk.z = sa.z >= 0.8f ? 1 : 0;
    mk.w = sa.w >= 0.8f ? 1 : 0;
    *(uchar4*)(g_mask + idx) = mk;
    int cnt = (int)mk.x + mk.y + mk.z + mk.w;
    unsigned tot = __reduce_add_sync(0xffffffffu, (unsigned)cnt);
    if ((t & 31) == 0 && tot) atomicAdd(&g_np, tot);
}

// ---------------- K45: gamma/beta conv blocks (0..511) + stats blocks (512..2559) ----------------
#define CONV_BLOCKS 512
#define STAT_BLOCKS (BN*CC*4)
__global__ void __launch_bounds__(256, 8) k45_fused(const float* __restrict__ x,
                                                    const float* __restrict__ wg, const float* __restrict__ bg,
                                                    const float* __restrict__ wb, const float* __restrict__ bb) {
    const int bx = blockIdx.x;
    const int t  = threadIdx.x;

    if (bx >= CONV_BLOCKS) {
        // ---- stats path ----
        const int sb    = bx - CONV_BLOCKS;
        const int chunk = sb & 3;
        const int c     = (sb >> 2) & 63;
        const int b     = sb >> 8;
        const float* xp = x + (((size_t)(b * CC + c)) << 16) + chunk * 16384;
        const unsigned char* mp = g_mask + (b << 16) + chunk * 16384;
        float s1 = 0.f, q1 = 0.f, s2 = 0.f, q2 = 0.f;
#pragma unroll
        for (int g = 0; g < 4; g++) {
            float4 xv[4]; uchar4 mk[4];
#pragma unroll
            for (int j = 0; j < 4; j++) {
                int off = ((g * 4 + j) * 256 + t) * 4;
                xv[j] = *(const float4*)(xp + off);
                mk[j] = *(const uchar4*)(mp + off);
            }
#pragma unroll
            for (int j = 0; j < 4; j++) {
                float m, n;
                m = mk[j].x ? 1.f : 0.f; n = 1.f - m;
                s1 = fmaf(m, xv[j].x, s1); q1 = fmaf(m * xv[j].x, xv[j].x, q1);
                s2 = fmaf(n, xv[j].x, s2); q2 = fmaf(n * xv[j].x, xv[j].x, q2);
                m = mk[j].y ? 1.f : 0.f; n = 1.f - m;
                s1 = fmaf(m, xv[j].y, s1); q1 = fmaf(m * xv[j].y, xv[j].y, q1);
                s2 = fmaf(n, xv[j].y, s2); q2 = fmaf(n * xv[j].y, xv[j].y, q2);
                m = mk[j].z ? 1.f : 0.f; n = 1.f - m;
                s1 = fmaf(m, xv[j].z, s1); q1 = fmaf(m * xv[j].z, xv[j].z, q1);
                s2 = fmaf(n, xv[j].z, s2); q2 = fmaf(n * xv[j].z, xv[j].z, q2);
                m = mk[j].w ? 1.f : 0.f; n = 1.f - m;
                s1 = fmaf(m, xv[j].w, s1); q1 = fmaf(m * xv[j].w, xv[j].w, q1);
                s2 = fmaf(n, xv[j].w, s2); q2 = fmaf(n * xv[j].w, xv[j].w, q2);
            }
        }
#pragma unroll
        for (int o = 16; o; o >>= 1) {
            s1 += __shfl_down_sync(0xffffffffu, s1, o);
            q1 += __shfl_down_sync(0xffffffffu, q1, o);
            s2 += __shfl_down_sync(0xffffffffu, s2, o);
            q2 += __shfl_down_sync(0xffffffffu, q2, o);
        }
        __shared__ float sh[8][4];
        int lane = t & 31, w = t >> 5;
        if (lane == 0) { sh[w][0] = s1; sh[w][1] = q1; sh[w][2] = s2; sh[w][3] = q2; }
        __syncthreads();
        if (t < 4) {
            float v = 0.f;
#pragma unroll
            for (int i = 0; i < 8; i++) v += sh[i][t];
            atomicAdd(&g_stats[c * 4 + t], (double)v);
        }
    } else {
        // ---- gamma/beta conv path: two 4-accumulator passes to fit 32 regs ----
        __shared__ float sSa[22][80];
        __shared__ float swt[98];     // [0..48]=wg, [49..97]=wb
        const int i  = bx;
        const int x0 = (i & 3) * 64;
        const int y0 = ((i >> 2) & 15) * 16;
        const int b  = i >> 6;
        if (t < 49)             swt[t] = wg[t];
        else if (t < 98)        swt[t] = wb[t - 49];
        const float* S = g_sa + b * MN;
        for (int j = t; j < 22 * 70; j += 256) {
            int sy = j / 70, sx = j % 70;
            int gy = y0 + sy - 3, gx = x0 + sx - 3;
            float v = 0.f;
            if ((unsigned)gy < 256u && (unsigned)gx < 256u) v = S[gy * 256 + gx];
            sSa[sy][sx] = v;
        }
        __syncthreads();
        const int row = t >> 4;
        const int cq  = (t & 15) * 4;
        const int idx = b * MN + (y0 + row) * 256 + x0 + cq;
#pragma unroll
        for (int pass = 0; pass < 2; pass++) {
            const float* wgt = &swt[pass * 49];
            float a0 = 0.f, a1 = 0.f, a2 = 0.f, a3 = 0.f;
#pragma unroll
            for (int ky = 0; ky < 7; ky++) {
                const float* rs = &sSa[row + ky][cq];
                float4 s0 = *(const float4*)rs;
                float4 s1 = *(const float4*)(rs + 4);
                float4 s2 = *(const float4*)(rs + 8);
                float sv[12] = {s0.x,s0.y,s0.z,s0.w,s1.x,s1.y,s1.z,s1.w,s2.x,s2.y,s2.z,s2.w};
#pragma unroll
                for (int kx = 0; kx < 7; kx++) {
                    float wv = wgt[ky*7 + kx];
                    a0 = fmaf(sv[kx  ], wv, a0);
                    a1 = fmaf(sv[kx+1], wv, a1);
                    a2 = fmaf(sv[kx+2], wv, a2);
                    a3 = fmaf(sv[kx+3], wv, a3);
                }
            }
            if (pass == 0) {
                const float bgv = bg[0];
                float4 go; go.x = a0 + bgv; go.y = a1 + bgv; go.z = a2 + bgv; go.w = a3 + bgv;
                *(float4*)(g_gam + idx) = go;
            } else {
                const float bbv = bb[0];
                float4 bo; bo.x = a0 + bbv; bo.y = a1 + bbv; bo.z = a2 + bbv; bo.w = a3 + bbv;
                *(float4*)(g_bet + idx) = bo;
            }
        }
    }
}

// ---------------- K6: params (fp32) + fused output; 1 quad/thread, 32 channels/block ----------------
__global__ void __launch_bounds__(256, 8) k6_out(const float* __restrict__ x, float* __restrict__ out) {
    __shared__ float4 sp[CC];
    const int t = threadIdx.x;
    if (t < CC) {
        float s1 = (float)g_stats[t*4+0], q1 = (float)g_stats[t*4+1];
        float s2 = (float)g_stats[t*4+2], q2 = (float)g_stats[t*4+3];
        float np = (float)g_np;
        float nq = (float)TOTPIX - np;
        float Sr1 = np > 0.f ? np : 1.f;
        float Sr2 = nq > 0.f ? nq : 1.f;
        float mu1 = s1 / Sr1, mu2 = s2 / Sr2;
        const float nt = (float)TOTPIX;
        float v1 = (q1 - s1 * mu1) / nt;
        float v2 = (q2 - s2 * mu2) / nt;
        v1 = fmaxf(v1, 0.f);
        v2 = fmaxf(v2, 0.f);
        float a1 = sqrtf(Sr1 / nt) * rsqrtf(v1 + 1e-5f);
        float a2 = sqrtf(Sr2 / nt) * rsqrtf(v2 + 1e-5f);
        float4 p; p.x = mu1; p.y = a1; p.z = mu2; p.w = a2;
        sp[t] = p;
    }
    __syncthreads();
    const int tid  = blockIdx.x * 256 + t;
    const int base = tid * 4;
    const int b    = base >> 16;
    const int pix  = base & (MN - 1);
    const int c0   = blockIdx.y * 32;               // channel group: 0 or 32

    uchar4 mk = *(const uchar4*)(g_mask + base);
    float4 gm = *(const float4*)(g_gam + base);
    float4 bt = *(const float4*)(g_bet + base);
    float g0 = 1.f + gm.x, g1 = 1.f + gm.y, g2 = 1.f + gm.z, g3 = 1.f + gm.w;
    const float* xb = x   + ((size_t)(b * CC + c0) << 16) + pix;
    float*       ob = out + ((size_t)(b * CC + c0) << 16) + pix;
#pragma unroll 4
    for (int c = 0; c < 32; c++) {
        float4 xv = *(const float4*)(xb + ((size_t)c << 16));
        float4 p  = sp[c0 + c];
        float4 o;
        float mu, a;
        mu = mk.x ? p.x : p.z; a = mk.x ? p.y : p.w; o.x = (xv.x - mu) * (a * g0) + bt.x;
        mu = mk.y ? p.x : p.z; a = mk.y ? p.y : p.w; o.y = (xv.y - mu) * (a * g1) + bt.y;
        mu = mk.z ? p.x : p.z; a = mk.z ? p.y : p.w; o.z = (xv.z - mu) * (a * g2) + bt.z;
        mu = mk.w ? p.x : p.z; a = mk.w ? p.y : p.w; o.w = (xv.w - mu) * (a * g3) + bt.w;
        *(float4*)(ob + ((size_t)c << 16)) = o;
    }
}

extern "C" void kernel_launch(void* const* d_in, const int* in_sizes, int n_in,
                              void* d_out, int out_size) {
    const float* x  = (const float*)d_in[0];
    const float* w1 = (const float*)d_in[1];
    const float* wg = (const float*)d_in[2];
    const float* bg = (const float*)d_in[3];
    const float* wb = (const float*)d_in[4];
    const float* bb = (const float*)d_in[5];
    float* out = (float*)d_out;

    k1_avgmax<<<TOTPIX / 1024, 256>>>(x);
    k23s_conv<<<dim3(4, 16, BN), 256>>>(w1);
    k45_fused<<<CONV_BLOCKS + STAT_BLOCKS, 256>>>(x, wg, bg, wb, bb);
    k6_out<<<dim3(TOTPIX / 1024, 2), 256>>>(x, out);
}

// round 17
// speedup vs baseline: 1.0361x; 1.0191x over previous
#include <cuda_runtime.h>

#define BN 8
#define CC 64
#define MM 256
#define NNX 256
#define MN (MM*NNX)          // 65536
#define TOTPIX (BN*MN)       // 524288

__device__ float g_avg[TOTPIX];
__device__ float g_mx [TOTPIX];
__device__ float g_sa [TOTPIX];
__device__ float g_gam[TOTPIX];
__device__ float g_bet[TOTPIX];
__device__ unsigned char g_mask[TOTPIX];
__device__ double g_stats[CC*4];      // s1, q1, s2, q2 per channel
__device__ unsigned int g_np;

// ---------------- K1: channel avg + max, 4 px/thread, 8-deep load batches ----------------
__global__ void __launch_bounds__(256, 4) k1_avgmax(const float* __restrict__ x) {
    const int t = threadIdx.x;
    if (blockIdx.x == 0) {
        if (t < CC*4) g_stats[t] = 0.0;
        if (t == 0)   g_np = 0u;
    }
    const int tid  = blockIdx.x * 256 + t;
    const int base = tid * 4;
    const int b    = base >> 16;
    const int pix  = base & (MN - 1);
    const float* xb = x + ((size_t)b << 22) + pix;

    float4 s, mx;
#pragma unroll
    for (int g = 0; g < 8; g++) {
        float4 v[8];
#pragma unroll
        for (int j = 0; j < 8; j++)
            v[j] = *(const float4*)(xb + ((size_t)(g * 8 + j) << 16));
#pragma unroll
        for (int j = 0; j < 8; j++) {
            if (g == 0 && j == 0) { s = v[0]; mx = v[0]; }
            else {
                s.x += v[j].x; s.y += v[j].y; s.z += v[j].z; s.w += v[j].w;
                mx.x = fmaxf(mx.x, v[j].x); mx.y = fmaxf(mx.y, v[j].y);
                mx.z = fmaxf(mx.z, v[j].z); mx.w = fmaxf(mx.w, v[j].w);
            }
        }
    }
    const float inv = 1.0f / 64.0f;
    float4 a; a.x = s.x*inv; a.y = s.y*inv; a.z = s.z*inv; a.w = s.w*inv;
    *(float4*)(g_avg + base) = a;
    *(float4*)(g_mx  + base) = mx;
}

// ---------------- K23s: sa conv + mask + Np only (1 quad/thread) ----------------
__global__ void k23s_conv(const float* __restrict__ w1) {
    __shared__ float sAvg[22][80];
    __shared__ float sMax[22][80];
    __shared__ float sw1[98];
    const int b  = blockIdx.z;
    const int x0 = blockIdx.x * 64, y0 = blockIdx.y * 16;
    const int t  = threadIdx.x;
    if (t < 98) sw1[t] = w1[t];   // independent of producer

#if __CUDA_ARCH__ >= 900
    cudaGridDependencySynchronize();
#endif

    const float* A = g_avg + b * MN;
    const float* X = g_mx  + b * MN;
    for (int i = t; i < 22 * 70; i += 256) {
        int sy = i / 70, sx = i % 70;
        int gy = y0 + sy - 3, gx = x0 + sx - 3;
        float a = 0.f, m = 0.f;
        if ((unsigned)gy < 256u && (unsigned)gx < 256u) {
            int g = gy * 256 + gx; a = A[g]; m = X[g];
        }
        sAvg[sy][sx] = a; sMax[sy][sx] = m;
    }
    __syncthreads();

    const int row = t >> 4;          // 0..15
    const int cq  = (t & 15) * 4;    // 0..60
    float acc0 = 0.f, acc1 = 0.f, acc2 = 0.f, acc3 = 0.f;
#pragma unroll
    for (int ky = 0; ky < 7; ky++) {
        const float* ra = &sAvg[row + ky][cq];
        const float* rm = &sMax[row + ky][cq];
        float4 a0 = *(const float4*)ra;
        float4 a1 = *(const float4*)(ra + 4);
        float4 a2 = *(const float4*)(ra + 8);
        float4 m0 = *(const float4*)rm;
        float4 m1 = *(const float4*)(rm + 4);
        float4 m2 = *(const float4*)(rm + 8);
        float av[12] = {a0.x,a0.y,a0.z,a0.w,a1.x,a1.y,a1.z,a1.w,a2.x,a2.y,a2.z,a2.w};
        float mv[12] = {m0.x,m0.y,m0.z,m0.w,m1.x,m1.y,m1.z,m1.w,m2.x,m2.y,m2.z,m2.w};
#pragma unroll
        for (int kx = 0; kx < 7; kx++) {
            float wa = sw1[ky*7 + kx], wm = sw1[49 + ky*7 + kx];
            acc0 = fmaf(av[kx  ], wa, acc0); acc0 = fmaf(mv[kx  ], wm, acc0);
            acc1 = fmaf(av[kx+1], wa, acc1); acc1 = fmaf(mv[kx+1], wm, acc1);
            acc2 = fmaf(av[kx+2], wa, acc2); acc2 = fmaf(mv[kx+2], wm, acc2);
            acc3 = fmaf(av[kx+3], wa, acc3); acc3 = fmaf(mv[kx+3], wm, acc3);
        }
    }
    float4 sa;
    sa.x = 1.f / (1.f + expf(-acc0));
    sa.y = 1.f / (1.f + expf(-acc1));
    sa.z = 1.f / (1.f + expf(-acc2));
    sa.w = 1.f / (1.f + expf(-acc3));
    const int idx = b * MN + (y0 + row) * 256 + x0 + cq;
    *(float4*)(g_sa + idx) = sa;
    uchar4 mk;
    mk.x = sa.x >= 0.8f ? 1 : 0;
    mk.y = sa.y >= 0.8f ? 1 : 0;
    mk.z = sa.z >= 0.8f ? 1 : 0;
    mk.w = sa.w >= 0.8f ? 1 : 0;
    *(uchar4*)(g_mask + idx) = mk;
    int cnt = (int)mk.x + mk.y + mk.z + mk.w;
    unsigned tot = __reduce_add_sync(0xffffffffu, (unsigned)cnt);
    if ((t & 31) == 0 && tot) atomicAdd(&g_np, tot);
}

// ---------------- K45: gamma/beta conv blocks (0..511) + stats blocks (512..2559) ----------------
#define CONV_BLOCKS 512
#define STAT_BLOCKS (BN*CC*4)
__global__ void __launch_bounds__(256, 8) k45_fused(const float* __restrict__ x,
                                                    const float* __restrict__ wg, const float* __restrict__ bg,
                                                    const float* __restrict__ wb, const float* __restrict__ bb) {
    const int bx = blockIdx.x;
    const int t  = threadIdx.x;

    if (bx >= CONV_BLOCKS) {
        // ---- stats path ----
        const int sb    = bx - CONV_BLOCKS;
        const int chunk = sb & 3;
        const int c     = (sb >> 2) & 63;
        const int b     = sb >> 8;
        const float* xp = x + (((size_t)(b * CC + c)) << 16) + chunk * 16384;
        const unsigned char* mp = g_mask + (b << 16) + chunk * 16384;
#if __CUDA_ARCH__ >= 900
        cudaGridDependencySynchronize();
#endif
        float s1 = 0.f, q1 = 0.f, s2 = 0.f, q2 = 0.f;
#pragma unroll
        for (int g = 0; g < 4; g++) {
            float4 xv[4]; uchar4 mk[4];
#pragma unroll
            for (int j = 0; j < 4; j++) {
                int off = ((g * 4 + j) * 256 + t) * 4;
                xv[j] = *(const float4*)(xp + off);
                mk[j] = *(const uchar4*)(mp + off);
            }
#pragma unroll
            for (int j = 0; j < 4; j++) {
                float m, n;
                m = mk[j].x ? 1.f : 0.f; n = 1.f - m;
                s1 = fmaf(m, xv[j].x, s1); q1 = fmaf(m * xv[j].x, xv[j].x, q1);
                s2 = fmaf(n, xv[j].x, s2); q2 = fmaf(n * xv[j].x, xv[j].x, q2);
                m = mk[j].y ? 1.f : 0.f; n = 1.f - m;
                s1 = fmaf(m, xv[j].y, s1); q1 = fmaf(m * xv[j].y, xv[j].y, q1);
                s2 = fmaf(n, xv[j].y, s2); q2 = fmaf(n * xv[j].y, xv[j].y, q2);
                m = mk[j].z ? 1.f : 0.f; n = 1.f - m;
                s1 = fmaf(m, xv[j].z, s1); q1 = fmaf(m * xv[j].z, xv[j].z, q1);
                s2 = fmaf(n, xv[j].z, s2); q2 = fmaf(n * xv[j].z, xv[j].z, q2);
                m = mk[j].w ? 1.f : 0.f; n = 1.f - m;
                s1 = fmaf(m, xv[j].w, s1); q1 = fmaf(m * xv[j].w, xv[j].w, q1);
                s2 = fmaf(n, xv[j].w, s2); q2 = fmaf(n * xv[j].w, xv[j].w, q2);
            }
        }
#pragma unroll
        for (int o = 16; o; o >>= 1) {
            s1 += __shfl_down_sync(0xffffffffu, s1, o);
            q1 += __shfl_down_sync(0xffffffffu, q1, o);
            s2 += __shfl_down_sync(0xffffffffu, s2, o);
            q2 += __shfl_down_sync(0xffffffffu, q2, o);
        }
        __shared__ float sh[8][4];
        int lane = t & 31, w = t >> 5;
        if (lane == 0) { sh[w][0] = s1; sh[w][1] = q1; sh[w][2] = s2; sh[w][3] = q2; }
        __syncthreads();
        if (t < 4) {
            float v = 0.f;
#pragma unroll
            for (int i = 0; i < 8; i++) v += sh[i][t];
            atomicAdd(&g_stats[c * 4 + t], (double)v);
        }
    } else {
        // ---- gamma/beta conv path: two 4-accumulator passes to fit 32 regs ----
        __shared__ float sSa[22][80];
        __shared__ float swt[98];     // [0..48]=wg, [49..97]=wb
        const int i  = bx;
        const int x0 = (i & 3) * 64;
        const int y0 = ((i >> 2) & 15) * 16;
        const int b  = i >> 6;
        if (t < 49)             swt[t] = wg[t];
        else if (t < 98)        swt[t] = wb[t - 49];
#if __CUDA_ARCH__ >= 900
        cudaGridDependencySynchronize();
#endif
        const float* S = g_sa + b * MN;
        for (int j = t; j < 22 * 70; j += 256) {
            int sy = j / 70, sx = j % 70;
            int gy = y0 + sy - 3, gx = x0 + sx - 3;
            float v = 0.f;
            if ((unsigned)gy < 256u && (unsigned)gx < 256u) v = S[gy * 256 + gx];
            sSa[sy][sx] = v;
        }
        __syncthreads();
        const int row = t >> 4;
        const int cq  = (t & 15) * 4;
        const int idx = b * MN + (y0 + row) * 256 + x0 + cq;
#pragma unroll
        for (int pass = 0; pass < 2; pass++) {
            const float* wgt = &swt[pass * 49];
            float a0 = 0.f, a1 = 0.f, a2 = 0.f, a3 = 0.f;
#pragma unroll
            for (int ky = 0; ky < 7; ky++) {
                const float* rs = &sSa[row + ky][cq];
                float4 s0 = *(const float4*)rs;
                float4 s1 = *(const float4*)(rs + 4);
                float4 s2 = *(const float4*)(rs + 8);
                float sv[12] = {s0.x,s0.y,s0.z,s0.w,s1.x,s1.y,s1.z,s1.w,s2.x,s2.y,s2.z,s2.w};
#pragma unroll
                for (int kx = 0; kx < 7; kx++) {
                    float wv = wgt[ky*7 + kx];
                    a0 = fmaf(sv[kx  ], wv, a0);
                    a1 = fmaf(sv[kx+1], wv, a1);
                    a2 = fmaf(sv[kx+2], wv, a2);
                    a3 = fmaf(sv[kx+3], wv, a3);
                }
            }
            if (pass == 0) {
                const float bgv = bg[0];
                float4 go; go.x = a0 + bgv; go.y = a1 + bgv; go.z = a2 + bgv; go.w = a3 + bgv;
                *(float4*)(g_gam + idx) = go;
            } else {
                const float bbv = bb[0];
                float4 bo; bo.x = a0 + bbv; bo.y = a1 + bbv; bo.z = a2 + bbv; bo.w = a3 + bbv;
                *(float4*)(g_bet + idx) = bo;
            }
        }
    }
}

// ---------------- K6: params (fp32) + fused output; 1 quad/thread, 32 channels/block ----------------
__global__ void __launch_bounds__(256, 8) k6_out(const float* __restrict__ x, float* __restrict__ out) {
    __shared__ float4 sp[CC];
    const int t = threadIdx.x;
#if __CUDA_ARCH__ >= 900
    cudaGridDependencySynchronize();
#endif
    if (t < CC) {
        float s1 = (float)g_stats[t*4+0], q1 = (float)g_stats[t*4+1];
        float s2 = (float)g_stats[t*4+2], q2 = (float)g_stats[t*4+3];
        float np = (float)g_np;
        float nq = (float)TOTPIX - np;
        float Sr1 = np > 0.f ? np : 1.f;
        float Sr2 = nq > 0.f ? nq : 1.f;
        float mu1 = s1 / Sr1, mu2 = s2 / Sr2;
        const float nt = (float)TOTPIX;
        float v1 = (q1 - s1 * mu1) / nt;
        float v2 = (q2 - s2 * mu2) / nt;
        v1 = fmaxf(v1, 0.f);
        v2 = fmaxf(v2, 0.f);
        float a1 = sqrtf(Sr1 / nt) * rsqrtf(v1 + 1e-5f);
        float a2 = sqrtf(Sr2 / nt) * rsqrtf(v2 + 1e-5f);
        float4 p; p.x = mu1; p.y = a1; p.z = mu2; p.w = a2;
        sp[t] = p;
    }
    __syncthreads();
    const int tid  = blockIdx.x * 256 + t;
    const int base = tid * 4;
    const int b    = base >> 16;
    const int pix  = base & (MN - 1);
    const int c0   = blockIdx.y * 32;               // channel group: 0 or 32

    uchar4 mk = *(const uchar4*)(g_mask + base);
    float4 gm = *(const float4*)(g_gam + base);
    float4 bt = *(const float4*)(g_bet + base);
    float g0 = 1.f + gm.x, g1 = 1.f + gm.y, g2 = 1.f + gm.z, g3 = 1.f + gm.w;
    const float* xb = x   + ((size_t)(b * CC + c0) << 16) + pix;
    float*       ob = out + ((size_t)(b * CC + c0) << 16) + pix;
#pragma unroll 4
    for (int c = 0; c < 32; c++) {
        float4 xv = *(const float4*)(xb + ((size_t)c << 16));
        float4 p  = sp[c0 + c];
        float4 o;
        float mu, a;
        mu = mk.x ? p.x : p.z; a = mk.x ? p.y : p.w; o.x = (xv.x - mu) * (a * g0) + bt.x;
        mu = mk.y ? p.x : p.z; a = mk.y ? p.y : p.w; o.y = (xv.y - mu) * (a * g1) + bt.y;
        mu = mk.z ? p.x : p.z; a = mk.z ? p.y : p.w; o.z = (xv.z - mu) * (a * g2) + bt.z;
        mu = mk.w ? p.x : p.z; a = mk.w ? p.y : p.w; o.w = (xv.w - mu) * (a * g3) + bt.w;
        *(float4*)(ob + ((size_t)c << 16)) = o;
    }
}

// ---------------- host: PDL launches ----------------
template <typename... Args>
static void launch_pdl(void (*kernel)(Args...), dim3 grid, dim3 block, Args... args) {
    cudaLaunchConfig_t cfg = {};
    cfg.gridDim = grid;
    cfg.blockDim = block;
    cudaLaunchAttribute attr[1];
    attr[0].id = cudaLaunchAttributeProgrammaticStreamSerialization;
    attr[0].val.programmaticStreamSerializationAllowed = 1;
    cfg.attrs = attr;
    cfg.numAttrs = 1;
    cudaLaunchKernelEx(&cfg, kernel, args...);
}

extern "C" void kernel_launch(void* const* d_in, const int* in_sizes, int n_in,
                              void* d_out, int out_size) {
    const float* x  = (const float*)d_in[0];
    const float* w1 = (const float*)d_in[1];
    const float* wg = (const float*)d_in[2];
    const float* bg = (const float*)d_in[3];
    const float* wb = (const float*)d_in[4];
    const float* bb = (const float*)d_in[5];
    float* out = (float*)d_out;

    k1_avgmax<<<TOTPIX / 1024, 256>>>(x);
    launch_pdl(k23s_conv, dim3(4, 16, BN), dim3(256), (const float*)w1);
    launch_pdl(k45_fused, dim3(CONV_BLOCKS + STAT_BLOCKS), dim3(256),
               (const float*)x, (const float*)wg, (const float*)bg,
               (const float*)wb, (const float*)bb);
    launch_pdl(k6_out, dim3(TOTPIX / 1024, 2), dim3(256), (const float*)x, (float*)out);
}